// round 1
// baseline (speedup 1.0000x reference)
#include <cuda_runtime.h>
#include <math.h>

#define D_MODEL 1024
#define N_EXP   32
#define D_LOW   64
#define N_TOK   1024
#define OUT_ELEMS (N_TOK * D_MODEL)

// ---------------- scratch (static device globals; no allocation) -------------
__device__ float g_wr[N_EXP * D_MODEL];      // folded router weights [32][1024]
__device__ int   g_cnt[N_EXP];               // tokens routed to each expert
__device__ float g_sumprob[N_EXP];           // sum over tokens of softmax prob
__device__ int   g_btok[N_EXP * N_TOK];      // bucket: token ids per expert
__device__ float g_bwgt[N_EXP * N_TOK];      // bucket: normalized top-k weight

// ---------------- small helpers ----------------------------------------------
__device__ __forceinline__ float dot4(float4 a, float4 b) {
    return a.x * b.x + a.y * b.y + a.z * b.z + a.w * b.w;
}
__device__ __forceinline__ void fma4(float4& acc, float4 a, float b) {
    acc.x = fmaf(a.x, b, acc.x);
    acc.y = fmaf(a.y, b, acc.y);
    acc.z = fmaf(a.z, b, acc.z);
    acc.w = fmaf(a.w, b, acc.w);
}
__device__ __forceinline__ void fma44(float4& acc, float4 a, float4 b) {
    acc.x = fmaf(a.x, b.x, acc.x);
    acc.y = fmaf(a.y, b.y, acc.y);
    acc.z = fmaf(a.z, b.z, acc.z);
    acc.w = fmaf(a.w, b.w, acc.w);
}
__device__ __forceinline__ float gelu_exact(float v) {
    return 0.5f * v * (1.0f + erff(v * 0.70710678118654752440f));
}

// ---------------- K0: zero output + accumulators ------------------------------
__global__ void k0_init(float4* out4) {
    int idx = blockIdx.x * blockDim.x + threadIdx.x;   // 1024*256 = 262144 = OUT/4
    out4[idx] = make_float4(0.f, 0.f, 0.f, 0.f);
    if (blockIdx.x == 0 && threadIdx.x < N_EXP) {
        g_cnt[threadIdx.x] = 0;
        g_sumprob[threadIdx.x] = 0.f;
    }
}

// ---------------- K1: fold router_w into w_down -> g_wr ------------------------
// g_wr[e][d] = sum_l w_down[e*64+l][d] * r[l]
__global__ void k1_fold(const float* __restrict__ w_down,
                        const float* __restrict__ router_w) {
    __shared__ float rs[D_LOW];
    int tid = threadIdx.x;
    if (tid < D_LOW) rs[tid] = router_w[tid];
    __syncthreads();
    int idx = blockIdx.x * blockDim.x + tid;           // 128*256 = 32768 = 32*1024
    int e = idx >> 10;
    int d = idx & (D_MODEL - 1);
    const float* wb = w_down + (e << 6) * D_MODEL + d;
    float acc = 0.f;
#pragma unroll 8
    for (int l = 0; l < D_LOW; l++)
        acc = fmaf(wb[l * D_MODEL], rs[l], acc);
    g_wr[idx] = acc;
}

// ---------------- K2: logits, softmax, top-2, bucketize ------------------------
// one block per token, 128 threads
__global__ void k2_route(const float* __restrict__ x) {
    __shared__ float4 xs4[D_MODEL / 4];
    __shared__ float  lg[N_EXP];
    const int n = blockIdx.x;
    const int tid = threadIdx.x;
    const int lane = tid & 31, warp = tid >> 5;

    const float4* xr = (const float4*)(x + n * D_MODEL);
    xs4[tid] = xr[tid];
    xs4[tid + 128] = xr[tid + 128];
    __syncthreads();

    // each warp handles 8 experts, warp-cooperative dot (coalesced g_wr reads)
#pragma unroll
    for (int ei = 0; ei < 8; ei++) {
        int e = warp * 8 + ei;
        const float4* wr = ((const float4*)g_wr) + e * (D_MODEL / 4);
        float acc = 0.f;
#pragma unroll
        for (int i = 0; i < 8; i++)
            acc += dot4(xs4[i * 32 + lane], wr[i * 32 + lane]);
#pragma unroll
        for (int o = 16; o; o >>= 1)
            acc += __shfl_xor_sync(0xffffffffu, acc, o);
        if (lane == 0) lg[e] = acc;
    }
    __syncthreads();

    if (tid < 32) {
        float v = lg[tid];
        // softmax over 32 experts
        float m = v;
#pragma unroll
        for (int o = 16; o; o >>= 1) m = fmaxf(m, __shfl_xor_sync(0xffffffffu, m, o));
        float ex = expf(v - m);
        float s = ex;
#pragma unroll
        for (int o = 16; o; o >>= 1) s += __shfl_xor_sync(0xffffffffu, s, o);
        float prob = ex / s;
        atomicAdd(&g_sumprob[tid], prob);

        // argmax (by logit; monotone with prob), tie -> lower index
        float bv = v; int bi = tid;
#pragma unroll
        for (int o = 16; o; o >>= 1) {
            float ov = __shfl_xor_sync(0xffffffffu, bv, o);
            int   oi = __shfl_xor_sync(0xffffffffu, bi, o);
            if (ov > bv || (ov == bv && oi < bi)) { bv = ov; bi = oi; }
        }
        int i0 = bi;
        float v2 = (tid == i0) ? -INFINITY : v;
        float bv2 = v2; int bi2 = tid;
#pragma unroll
        for (int o = 16; o; o >>= 1) {
            float ov = __shfl_xor_sync(0xffffffffu, bv2, o);
            int   oi = __shfl_xor_sync(0xffffffffu, bi2, o);
            if (ov > bv2 || (ov == bv2 && oi < bi2)) { bv2 = ov; bi2 = oi; }
        }
        int i1 = bi2;
        float p0 = __shfl_sync(0xffffffffu, prob, i0);
        float p1 = __shfl_sync(0xffffffffu, prob, i1);
        if (tid == 0) {
            float inv = 1.f / (p0 + p1);
            int s0 = atomicAdd(&g_cnt[i0], 1);
            g_btok[i0 * N_TOK + s0] = n;
            g_bwgt[i0 * N_TOK + s0] = p0 * inv;
            int s1 = atomicAdd(&g_cnt[i1], 1);
            g_btok[i1 * N_TOK + s1] = n;
            g_bwgt[i1 * N_TOK + s1] = p1 * inv;
        }
    }
}

// ---------------- K4: fused per-expert down-proj + GELU + up-proj + scatter ----
// grid (64 token-tiles, 32 experts), 256 threads. Tile = 16 tokens.
#define TTILE 16
__global__ __launch_bounds__(256, 2)
void k4_expert(const float* __restrict__ x,
               const float* __restrict__ w_down,
               const float* __restrict__ w_up,
               float* __restrict__ out) {
    const int e = blockIdx.y;
    const int cnt = g_cnt[e];
    const int t0 = blockIdx.x * TTILE;
    if (t0 >= cnt) return;

    __shared__ float4 ws4[D_LOW * 33];        // [64][132 floats], stride 33 f4
    __shared__ float4 xs4[TTILE * 33];        // [16][132 floats]
    __shared__ float  acts[TTILE * 65];       // [16][65]
    __shared__ int    tokS[TTILE];
    __shared__ float  wgtS[TTILE];

    const int tid = threadIdx.x;
    if (tid < TTILE) {
        int idx = t0 + tid;
        if (idx < cnt) { tokS[tid] = g_btok[e * N_TOK + idx]; wgtS[tid] = g_bwgt[e * N_TOK + idx]; }
        else           { tokS[tid] = 0;                       wgtS[tid] = 0.f; }
    }
    __syncthreads();

    const int lane = tid & 31, warp = tid >> 5;
    const int t = lane & 15;           // token index within tile
    const int lhalf = lane >> 4;       // 0/1
    // this thread's 4 low-dim outputs: l_j = warp*8 + 2*j + lhalf

    float4 a0 = make_float4(0, 0, 0, 0), a1 = a0, a2 = a0, a3 = a0;
    const float4* x4g = (const float4*)x;
    const float4* wd4 = (const float4*)w_down;

    // --- phase 1: feats[t][l] = x[tok[t]] . w_down[e*64+l], K chunked by 128 ---
    for (int kc = 0; kc < 8; kc++) {
        const int k0q = kc * 32;       // f4 offset in the 1024-dim row
#pragma unroll
        for (int i = 0; i < 2; i++) {  // 16 rows x 32 f4 of x
            int qq = tid + i * 256;
            int tr = qq >> 5, kq = qq & 31;
            xs4[tr * 33 + kq] = x4g[tokS[tr] * (D_MODEL / 4) + k0q + kq];
        }
#pragma unroll
        for (int i = 0; i < 8; i++) {  // 64 rows x 32 f4 of w_down_e
            int qq = tid + i * 256;
            int lr = qq >> 5, kq = qq & 31;
            ws4[lr * 33 + kq] = wd4[(e * D_LOW + lr) * (D_MODEL / 4) + k0q + kq];
        }
        __syncthreads();
#pragma unroll 8
        for (int k4 = 0; k4 < 32; k4++) {
            float4 xv = xs4[t * 33 + k4];
            fma44(a0, xv, ws4[(warp * 8 + 0 + lhalf) * 33 + k4]);
            fma44(a1, xv, ws4[(warp * 8 + 2 + lhalf) * 33 + k4]);
            fma44(a2, xv, ws4[(warp * 8 + 4 + lhalf) * 33 + k4]);
            fma44(a3, xv, ws4[(warp * 8 + 6 + lhalf) * 33 + k4]);
        }
        __syncthreads();
    }
    // reduce + GELU -> acts
    {
        float f0 = a0.x + a0.y + a0.z + a0.w;
        float f1 = a1.x + a1.y + a1.z + a1.w;
        float f2 = a2.x + a2.y + a2.z + a2.w;
        float f3 = a3.x + a3.y + a3.z + a3.w;
        acts[t * 65 + warp * 8 + 0 + lhalf] = gelu_exact(f0);
        acts[t * 65 + warp * 8 + 2 + lhalf] = gelu_exact(f1);
        acts[t * 65 + warp * 8 + 4 + lhalf] = gelu_exact(f2);
        acts[t * 65 + warp * 8 + 6 + lhalf] = gelu_exact(f3);
    }

    // --- phase 2: out[tok[t]] += wgt[t] * acts[t] @ w_up[e], D chunked by 128 ---
    const int dq = tid & 31;           // f4 column within chunk
    const int tg = tid >> 5;           // 0..7 -> tokens {2tg, 2tg+1}
    const int tA = tg * 2, tB = tg * 2 + 1;
    const float4* wu4 = (const float4*)w_up;

    for (int dc = 0; dc < 8; dc++) {
        const int d0q = dc * 32;
        __syncthreads();               // prior readers of ws4 / acts done
#pragma unroll
        for (int i = 0; i < 8; i++) {  // 64 rows x 32 f4 of w_up_e chunk
            int qq = tid + i * 256;
            int lr = qq >> 5, kq = qq & 31;
            ws4[lr * 33 + kq] = wu4[(e * D_LOW + lr) * (D_MODEL / 4) + d0q + kq];
        }
        __syncthreads();

        float4 accA = make_float4(0, 0, 0, 0), accB = accA;
#pragma unroll 8
        for (int l = 0; l < D_LOW; l++) {
            float4 wv = ws4[l * 33 + dq];
            fma4(accA, wv, acts[tA * 65 + l]);
            fma4(accB, wv, acts[tB * 65 + l]);
        }
        const float wA = wgtS[tA], wB = wgtS[tB];
        const int dbase = dc * 128 + dq * 4;
        float* oA = out + tokS[tA] * D_MODEL + dbase;
        atomicAdd(oA + 0, wA * accA.x);
        atomicAdd(oA + 1, wA * accA.y);
        atomicAdd(oA + 2, wA * accA.z);
        atomicAdd(oA + 3, wA * accA.w);
        float* oB = out + tokS[tB] * D_MODEL + dbase;
        atomicAdd(oB + 0, wB * accB.x);
        atomicAdd(oB + 1, wB * accB.y);
        atomicAdd(oB + 2, wB * accB.z);
        atomicAdd(oB + 3, wB * accB.w);
    }
}

// ---------------- K5: aux load-balancing loss ---------------------------------
__global__ void k5_aux(float* out, int write_aux) {
    int tid = threadIdx.x;
    float v = g_sumprob[tid] * (float)g_cnt[tid];
#pragma unroll
    for (int o = 16; o; o >>= 1) v += __shfl_xor_sync(0xffffffffu, v, o);
    if (tid == 0 && write_aux)
        out[OUT_ELEMS] = (float)N_EXP * v / ((float)N_TOK * (float)N_TOK);
}

// ---------------- launch ------------------------------------------------------
extern "C" void kernel_launch(void* const* d_in, const int* in_sizes, int n_in,
                              void* d_out, int out_size) {
    const float* x        = (const float*)d_in[0];
    const float* w_down   = (const float*)d_in[1];
    const float* router_w = (const float*)d_in[2];
    const float* w_up     = (const float*)d_in[3];
    float* out = (float*)d_out;

    k0_init<<<1024, 256>>>((float4*)out);
    k1_fold<<<128, 256>>>(w_down, router_w);
    k2_route<<<N_TOK, 128>>>(x);
    k4_expert<<<dim3(64, 32), 256>>>(x, w_down, w_up, out);
    k5_aux<<<1, 32>>>(out, out_size > OUT_ELEMS ? 1 : 0);
}

// round 2
// speedup vs baseline: 1.1216x; 1.1216x over previous
#include <cuda_runtime.h>
#include <math.h>

#define D_MODEL 1024
#define N_EXP   32
#define D_LOW   64
#define N_TOK   1024
#define N_PAIR  (N_TOK * 2)
#define OUT_ELEMS (N_TOK * D_MODEL)

// ---------------- scratch (static device globals; no allocation) -------------
__device__ float g_wr[N_EXP * D_MODEL];      // folded router weights [32][1024]
__device__ int   g_cnt[N_EXP];               // tokens routed to each expert
__device__ float g_sumprob[N_EXP];           // sum over tokens of softmax prob
__device__ int   g_off[N_EXP];               // exclusive prefix of g_cnt
__device__ int   g_btok[N_EXP * N_TOK];      // bucket: token ids per expert
__device__ float g_bwgt[N_EXP * N_TOK];      // bucket: normalized top-k weight
__device__ int   g_pslot[N_TOK * 2];         // token -> packed (e*N_TOK + slot)
__device__ float g_actp0[N_PAIR * D_LOW];    // K-split partial feats (lo half)
__device__ float g_actp1[N_PAIR * D_LOW];    // K-split partial feats (hi half)
__device__ float g_acts[N_PAIR * D_LOW];     // gelu(feats), pair-compact
__device__ float g_y[N_PAIR * D_MODEL];      // weighted per-pair up-proj output

// ---------------- small helpers ----------------------------------------------
__device__ __forceinline__ float dot4(float4 a, float4 b) {
    return a.x * b.x + a.y * b.y + a.z * b.z + a.w * b.w;
}
__device__ __forceinline__ void fma4(float4& acc, float4 a, float b) {
    acc.x = fmaf(a.x, b, acc.x);
    acc.y = fmaf(a.y, b, acc.y);
    acc.z = fmaf(a.z, b, acc.z);
    acc.w = fmaf(a.w, b, acc.w);
}
__device__ __forceinline__ void fma44(float4& acc, float4 a, float4 b) {
    acc.x = fmaf(a.x, b.x, acc.x);
    acc.y = fmaf(a.y, b.y, acc.y);
    acc.z = fmaf(a.z, b.z, acc.z);
    acc.w = fmaf(a.w, b.w, acc.w);
}
__device__ __forceinline__ float gelu_exact(float v) {
    return 0.5f * v * (1.0f + erff(v * 0.70710678118654752440f));
}

// ---------------- K1: fold router_w into w_down -> g_wr; zero accumulators ----
__global__ void k1_fold(const float* __restrict__ w_down,
                        const float* __restrict__ router_w) {
    __shared__ float rs[D_LOW];
    int tid = threadIdx.x;
    if (blockIdx.x == 0 && tid < N_EXP) { g_cnt[tid] = 0; g_sumprob[tid] = 0.f; }
    if (tid < D_LOW) rs[tid] = router_w[tid];
    __syncthreads();
    int idx = blockIdx.x * 256 + tid;                  // 128*256 = 32768 = 32*1024
    int e = idx >> 10;
    int d = idx & (D_MODEL - 1);
    const float* wb = w_down + (e << 6) * D_MODEL + d;
    float acc = 0.f;
#pragma unroll 8
    for (int l = 0; l < D_LOW; l++)
        acc = fmaf(wb[l * D_MODEL], rs[l], acc);
    g_wr[idx] = acc;
}

// ---------------- K2: tiled logits GEMM + softmax + top-2 + bucketize ---------
// 32 blocks x 256 threads; block handles 32 tokens x all 32 experts.
__global__ __launch_bounds__(256) void k2_route(const float* __restrict__ x) {
    __shared__ float4 xs4[32 * 33];
    __shared__ float4 wr4[32 * 33];
    __shared__ float  lg[32 * 33];      // [tok][exp]
    const int tid = threadIdx.x;
    const int b = blockIdx.x;
    const int t = tid & 31, eg = tid >> 5;
    const float4* x4 = (const float4*)x;
    const float4* w4 = (const float4*)g_wr;

    float acc0 = 0.f, acc1 = 0.f, acc2 = 0.f, acc3 = 0.f;
    for (int kc = 0; kc < 8; kc++) {
        const int k0q = kc * 32;
#pragma unroll
        for (int i = 0; i < 4; i++) {
            int j = tid + i * 256;
            int r = j >> 5, c = j & 31;
            xs4[r * 33 + c] = x4[(b * 32 + r) * (D_MODEL / 4) + k0q + c];
            wr4[r * 33 + c] = w4[r * (D_MODEL / 4) + k0q + c];
        }
        __syncthreads();
#pragma unroll 8
        for (int k4 = 0; k4 < 32; k4++) {
            float4 xv = xs4[t * 33 + k4];
            acc0 += dot4(xv, wr4[(eg * 4 + 0) * 33 + k4]);
            acc1 += dot4(xv, wr4[(eg * 4 + 1) * 33 + k4]);
            acc2 += dot4(xv, wr4[(eg * 4 + 2) * 33 + k4]);
            acc3 += dot4(xv, wr4[(eg * 4 + 3) * 33 + k4]);
        }
        __syncthreads();
    }
    lg[t * 33 + eg * 4 + 0] = acc0;
    lg[t * 33 + eg * 4 + 1] = acc1;
    lg[t * 33 + eg * 4 + 2] = acc2;
    lg[t * 33 + eg * 4 + 3] = acc3;
    __syncthreads();

    // warp w handles tokens w*4 .. w*4+3 (lane = expert)
    const int lane = tid & 31, warp = tid >> 5;
    float spacc = 0.f;
#pragma unroll
    for (int j = 0; j < 4; j++) {
        const int tt = warp * 4 + j;
        const int n = b * 32 + tt;
        float v = lg[tt * 33 + lane];
        float m = v;
#pragma unroll
        for (int o = 16; o; o >>= 1) m = fmaxf(m, __shfl_xor_sync(0xffffffffu, m, o));
        float ex = expf(v - m);
        float s = ex;
#pragma unroll
        for (int o = 16; o; o >>= 1) s += __shfl_xor_sync(0xffffffffu, s, o);
        float prob = ex / s;
        spacc += prob;

        // top-1 by logit (monotone with prob), tie -> lower index
        float bv = v; int bi = lane;
#pragma unroll
        for (int o = 16; o; o >>= 1) {
            float ov = __shfl_xor_sync(0xffffffffu, bv, o);
            int   oi = __shfl_xor_sync(0xffffffffu, bi, o);
            if (ov > bv || (ov == bv && oi < bi)) { bv = ov; bi = oi; }
        }
        int i0 = bi;
        float v2 = (lane == i0) ? -INFINITY : v;
        float bv2 = v2; int bi2 = lane;
#pragma unroll
        for (int o = 16; o; o >>= 1) {
            float ov = __shfl_xor_sync(0xffffffffu, bv2, o);
            int   oi = __shfl_xor_sync(0xffffffffu, bi2, o);
            if (ov > bv2 || (ov == bv2 && oi < bi2)) { bv2 = ov; bi2 = oi; }
        }
        int i1 = bi2;
        float p0 = __shfl_sync(0xffffffffu, prob, i0);
        float p1 = __shfl_sync(0xffffffffu, prob, i1);
        if (lane == 0) {
            float inv = 1.f / (p0 + p1);
            int s0 = atomicAdd(&g_cnt[i0], 1);
            g_btok[i0 * N_TOK + s0] = n;
            g_bwgt[i0 * N_TOK + s0] = p0 * inv;
            g_pslot[n * 2 + 0] = i0 * N_TOK + s0;
            int s1 = atomicAdd(&g_cnt[i1], 1);
            g_btok[i1 * N_TOK + s1] = n;
            g_bwgt[i1 * N_TOK + s1] = p1 * inv;
            g_pslot[n * 2 + 1] = i1 * N_TOK + s1;
        }
    }
    atomicAdd(&g_sumprob[lane], spacc);
}

// ---------------- K2b: prefix offsets + aux loss ------------------------------
__global__ void k2b_prefix(float* out, int write_aux) {
    int lane = threadIdx.x;   // 32 threads
    int c = g_cnt[lane];
    int sc = c;
#pragma unroll
    for (int o = 1; o < 32; o <<= 1) {
        int v = __shfl_up_sync(0xffffffffu, sc, o);
        if (lane >= o) sc += v;
    }
    g_off[lane] = sc - c;
    if (write_aux) {
        float v = g_sumprob[lane] * (float)c;
#pragma unroll
        for (int o = 16; o; o >>= 1) v += __shfl_xor_sync(0xffffffffu, v, o);
        if (lane == 0)
            out[OUT_ELEMS] = (float)N_EXP * v / ((float)N_TOK * (float)N_TOK);
    }
}

// ---------------- K3: per-expert down-proj (K-split by 2), partial, no GELU ---
// grid (64 token-tiles, 32 experts, 2 k-halves), 256 threads, tile = 16 tokens.
#define TTILE 16
__global__ __launch_bounds__(256, 2)
void k3_down(const float* __restrict__ x, const float* __restrict__ w_down) {
    const int e = blockIdx.y;
    const int ks = blockIdx.z;
    const int cnt = g_cnt[e];
    const int t0 = blockIdx.x * TTILE;
    if (t0 >= cnt) return;

    __shared__ float4 ws4[D_LOW * 33];        // [64][132 floats]
    __shared__ float4 xs4[TTILE * 33];        // [16][132 floats]
    __shared__ int    tokS[TTILE];

    const int tid = threadIdx.x;
    if (tid < TTILE) {
        int idx = t0 + tid;
        tokS[tid] = (idx < cnt) ? g_btok[e * N_TOK + idx] : 0;
    }
    __syncthreads();

    const int lane = tid & 31, warp = tid >> 5;
    const int t = lane & 15;
    const int lhalf = lane >> 4;

    float4 a0 = make_float4(0, 0, 0, 0), a1 = a0, a2 = a0, a3 = a0;
    const float4* x4g = (const float4*)x;
    const float4* wd4 = (const float4*)w_down;

    for (int kc = ks * 4; kc < ks * 4 + 4; kc++) {
        const int k0q = kc * 32;
#pragma unroll
        for (int i = 0; i < 2; i++) {
            int qq = tid + i * 256;
            int tr = qq >> 5, kq = qq & 31;
            xs4[tr * 33 + kq] = x4g[tokS[tr] * (D_MODEL / 4) + k0q + kq];
        }
#pragma unroll
        for (int i = 0; i < 8; i++) {
            int qq = tid + i * 256;
            int lr = qq >> 5, kq = qq & 31;
            ws4[lr * 33 + kq] = wd4[(e * D_LOW + lr) * (D_MODEL / 4) + k0q + kq];
        }
        __syncthreads();
#pragma unroll 8
        for (int k4 = 0; k4 < 32; k4++) {
            float4 xv = xs4[t * 33 + k4];
            fma44(a0, xv, ws4[(warp * 8 + 0 + lhalf) * 33 + k4]);
            fma44(a1, xv, ws4[(warp * 8 + 2 + lhalf) * 33 + k4]);
            fma44(a2, xv, ws4[(warp * 8 + 4 + lhalf) * 33 + k4]);
            fma44(a3, xv, ws4[(warp * 8 + 6 + lhalf) * 33 + k4]);
        }
        __syncthreads();
    }

    if (t0 + t < cnt) {
        int pair = g_off[e] + t0 + t;
        float* dst = (ks ? g_actp1 : g_actp0) + pair * D_LOW;
        dst[warp * 8 + 0 + lhalf] = a0.x + a0.y + a0.z + a0.w;
        dst[warp * 8 + 2 + lhalf] = a1.x + a1.y + a1.z + a1.w;
        dst[warp * 8 + 4 + lhalf] = a2.x + a2.y + a2.z + a2.w;
        dst[warp * 8 + 6 + lhalf] = a3.x + a3.y + a3.z + a3.w;
    }
}

// ---------------- K3g: combine K-halves + GELU --------------------------------
__global__ void k3g_gelu() {
    int i = blockIdx.x * 256 + threadIdx.x;   // 512*256 = 131072 = N_PAIR*64
    g_acts[i] = gelu_exact(g_actp0[i] + g_actp1[i]);
}

// ---------------- K4: per-expert up-proj, weighted, written per-pair ----------
// grid (8 d-chunks, 32 experts), 256 threads. 128 d per chunk, 32 tokens/group.
__global__ __launch_bounds__(256, 2)
void k4_up(const float* __restrict__ w_up) {
    const int e = blockIdx.y;
    const int dc = blockIdx.x;
    const int cnt = g_cnt[e];
    if (cnt == 0) return;
    const int off = g_off[e];

    __shared__ float4 wu4s[D_LOW * 33];       // [64][132 floats]
    __shared__ float  acts_s[32 * 65];        // [32 tokens][64+pad]
    __shared__ float  wgt_s[32];

    const int tid = threadIdx.x;
    const float4* wu4 = (const float4*)w_up;
    const int d0q = dc * 32;
#pragma unroll
    for (int i = 0; i < 8; i++) {
        int j = tid + i * 256;
        int lr = j >> 5, kq = j & 31;
        wu4s[lr * 33 + kq] = wu4[(e * D_LOW + lr) * (D_MODEL / 4) + d0q + kq];
    }

    const int dq = tid & 31;
    const int tg = tid >> 5;
    float4* y4 = (float4*)g_y;

    for (int s0 = 0; s0 < cnt; s0 += 32) {
        __syncthreads();   // wu load done / previous compute done
        for (int j = tid; j < 32 * 64; j += 256) {
            int tt = j >> 6, l = j & 63;
            int s = s0 + tt;
            acts_s[tt * 65 + l] = (s < cnt) ? g_acts[(off + s) * D_LOW + l] : 0.f;
        }
        if (tid < 32) {
            int s = s0 + tid;
            wgt_s[tid] = (s < cnt) ? g_bwgt[e * N_TOK + s] : 0.f;
        }
        __syncthreads();

        float4 c0 = make_float4(0, 0, 0, 0), c1 = c0, c2 = c0, c3 = c0;
#pragma unroll 8
        for (int l = 0; l < D_LOW; l++) {
            float4 wv = wu4s[l * 33 + dq];
            fma4(c0, wv, acts_s[(tg +  0) * 65 + l]);
            fma4(c1, wv, acts_s[(tg +  8) * 65 + l]);
            fma4(c2, wv, acts_s[(tg + 16) * 65 + l]);
            fma4(c3, wv, acts_s[(tg + 24) * 65 + l]);
        }
#pragma unroll
        for (int j = 0; j < 4; j++) {
            int tt = tg + 8 * j;
            int s = s0 + tt;
            if (s < cnt) {
                float w = wgt_s[tt];
                float4 a = (j == 0) ? c0 : (j == 1) ? c1 : (j == 2) ? c2 : c3;
                float4 yv = make_float4(w * a.x, w * a.y, w * a.z, w * a.w);
                y4[(off + s) * (D_MODEL / 4) + d0q + dq] = yv;
            }
        }
    }
}

// ---------------- K5: gather-combine the two pairs per token ------------------
__global__ void k5_combine(float* __restrict__ out) {
    const int n = blockIdx.x;
    const int i = threadIdx.x;        // 256 = D_MODEL/4
    int v0 = g_pslot[n * 2 + 0];
    int v1 = g_pslot[n * 2 + 1];
    int p0 = g_off[v0 >> 10] + (v0 & (N_TOK - 1));
    int p1 = g_off[v1 >> 10] + (v1 & (N_TOK - 1));
    const float4* y4 = (const float4*)g_y;
    float4 a = y4[p0 * (D_MODEL / 4) + i];
    float4 b = y4[p1 * (D_MODEL / 4) + i];
    ((float4*)out)[n * (D_MODEL / 4) + i] =
        make_float4(a.x + b.x, a.y + b.y, a.z + b.z, a.w + b.w);
}

// ---------------- launch ------------------------------------------------------
extern "C" void kernel_launch(void* const* d_in, const int* in_sizes, int n_in,
                              void* d_out, int out_size) {
    const float* x        = (const float*)d_in[0];
    const float* w_down   = (const float*)d_in[1];
    const float* router_w = (const float*)d_in[2];
    const float* w_up     = (const float*)d_in[3];
    float* out = (float*)d_out;

    k1_fold<<<128, 256>>>(w_down, router_w);
    k2_route<<<32, 256>>>(x);
    k2b_prefix<<<1, 32>>>(out, out_size > OUT_ELEMS ? 1 : 0);
    k3_down<<<dim3(64, 32, 2), 256>>>(x, w_down);
    k3g_gelu<<<512, 256>>>();
    k4_up<<<dim3(8, 32), 256>>>(w_up);
    k5_combine<<<N_TOK, 256>>>(out);
}

// round 4
// speedup vs baseline: 1.2688x; 1.1312x over previous
#include <cuda_runtime.h>
#include <math.h>

#define D_MODEL 1024
#define N_EXP   32
#define D_LOW   64
#define N_TOK   1024
#define N_PAIR  (N_TOK * 2)
#define OUT_ELEMS (N_TOK * D_MODEL)
#define KSPLIT  16
#define PS      (N_PAIR * D_LOW)     // 131072 partial elems per k-slice

// ---------------- scratch ------------------------------------------------------
__device__ float g_wr[N_EXP * D_MODEL];
__device__ int   g_cnt[N_EXP];
__device__ float g_sumprob[N_EXP];
__device__ int   g_off[N_EXP];
__device__ int   g_btok[N_EXP * N_TOK];
__device__ float g_bwgt[N_EXP * N_TOK];
__device__ int   g_pslot[N_TOK * 2];
__device__ float g_actp[KSPLIT * PS];        // K-split down-proj partials (8MB)
__device__ float g_acts[PS];                 // gelu(feats), pair-compact
__device__ float g_y[N_PAIR * D_MODEL];      // weighted per-pair up-proj output

// ---------------- helpers ------------------------------------------------------
typedef unsigned long long ull;
#define FFMA2(acc, a, b) asm("fma.rn.f32x2 %0, %1, %2, %0;" : "+l"(acc) : "l"(a), "l"(b))

__device__ __forceinline__ float hsum2(ull v) {
    return __uint_as_float((unsigned)v) + __uint_as_float((unsigned)(v >> 32));
}
__device__ __forceinline__ float dot4(float4 a, float4 b) {
    return a.x * b.x + a.y * b.y + a.z * b.z + a.w * b.w;
}
__device__ __forceinline__ float gelu_exact(float v) {
    return 0.5f * v * (1.0f + erff(v * 0.70710678118654752440f));
}

// ---------------- K1: fold router_w into w_down -> g_wr; zero accumulators ----
__global__ void k1_fold(const float* __restrict__ w_down,
                        const float* __restrict__ router_w) {
    __shared__ float rs[D_LOW];
    int tid = threadIdx.x;
    if (blockIdx.x == 0 && tid < N_EXP) { g_cnt[tid] = 0; g_sumprob[tid] = 0.f; }
    if (tid < D_LOW) rs[tid] = router_w[tid];
    __syncthreads();
    int idx = blockIdx.x * 256 + tid;
    int e = idx >> 10;
    int d = idx & (D_MODEL - 1);
    const float* wb = w_down + (e << 6) * D_MODEL + d;
    float acc = 0.f;
#pragma unroll 8
    for (int l = 0; l < D_LOW; l++)
        acc = fmaf(wb[l * D_MODEL], rs[l], acc);
    g_wr[idx] = acc;
}

// ---------------- K2: tiled logits GEMM + softmax + top-2 + bucketize ---------
__global__ __launch_bounds__(256) void k2_route(const float* __restrict__ x) {
    __shared__ float4 xs4[32 * 33];
    __shared__ float4 wr4[32 * 33];
    __shared__ float  lg[32 * 33];
    const int tid = threadIdx.x;
    const int b = blockIdx.x;
    const int t = tid & 31, eg = tid >> 5;
    const float4* x4 = (const float4*)x;
    const float4* w4 = (const float4*)g_wr;

    float acc0 = 0.f, acc1 = 0.f, acc2 = 0.f, acc3 = 0.f;
    for (int kc = 0; kc < 8; kc++) {
        const int k0q = kc * 32;
#pragma unroll
        for (int i = 0; i < 4; i++) {
            int j = tid + i * 256;
            int r = j >> 5, c = j & 31;
            xs4[r * 33 + c] = x4[(b * 32 + r) * (D_MODEL / 4) + k0q + c];
            wr4[r * 33 + c] = w4[r * (D_MODEL / 4) + k0q + c];
        }
        __syncthreads();
#pragma unroll 8
        for (int k4 = 0; k4 < 32; k4++) {
            float4 xv = xs4[t * 33 + k4];
            acc0 += dot4(xv, wr4[(eg * 4 + 0) * 33 + k4]);
            acc1 += dot4(xv, wr4[(eg * 4 + 1) * 33 + k4]);
            acc2 += dot4(xv, wr4[(eg * 4 + 2) * 33 + k4]);
            acc3 += dot4(xv, wr4[(eg * 4 + 3) * 33 + k4]);
        }
        __syncthreads();
    }
    lg[t * 33 + eg * 4 + 0] = acc0;
    lg[t * 33 + eg * 4 + 1] = acc1;
    lg[t * 33 + eg * 4 + 2] = acc2;
    lg[t * 33 + eg * 4 + 3] = acc3;
    __syncthreads();

    const int lane = tid & 31, warp = tid >> 5;
    float spacc = 0.f;
#pragma unroll
    for (int j = 0; j < 4; j++) {
        const int tt = warp * 4 + j;
        const int n = b * 32 + tt;
        float v = lg[tt * 33 + lane];
        float m = v;
#pragma unroll
        for (int o = 16; o; o >>= 1) m = fmaxf(m, __shfl_xor_sync(0xffffffffu, m, o));
        float ex = expf(v - m);
        float s = ex;
#pragma unroll
        for (int o = 16; o; o >>= 1) s += __shfl_xor_sync(0xffffffffu, s, o);
        float prob = ex / s;
        spacc += prob;

        float bv = v; int bi = lane;
#pragma unroll
        for (int o = 16; o; o >>= 1) {
            float ov = __shfl_xor_sync(0xffffffffu, bv, o);
            int   oi = __shfl_xor_sync(0xffffffffu, bi, o);
            if (ov > bv || (ov == bv && oi < bi)) { bv = ov; bi = oi; }
        }
        int i0 = bi;
        float v2 = (lane == i0) ? -INFINITY : v;
        float bv2 = v2; int bi2 = lane;
#pragma unroll
        for (int o = 16; o; o >>= 1) {
            float ov = __shfl_xor_sync(0xffffffffu, bv2, o);
            int   oi = __shfl_xor_sync(0xffffffffu, bi2, o);
            if (ov > bv2 || (ov == bv2 && oi < bi2)) { bv2 = ov; bi2 = oi; }
        }
        int i1 = bi2;
        float p0 = __shfl_sync(0xffffffffu, prob, i0);
        float p1 = __shfl_sync(0xffffffffu, prob, i1);
        if (lane == 0) {
            float inv = 1.f / (p0 + p1);
            int s0 = atomicAdd(&g_cnt[i0], 1);
            g_btok[i0 * N_TOK + s0] = n;
            g_bwgt[i0 * N_TOK + s0] = p0 * inv;
            g_pslot[n * 2 + 0] = i0 * N_TOK + s0;
            int s1 = atomicAdd(&g_cnt[i1], 1);
            g_btok[i1 * N_TOK + s1] = n;
            g_bwgt[i1 * N_TOK + s1] = p1 * inv;
            g_pslot[n * 2 + 1] = i1 * N_TOK + s1;
        }
    }
    atomicAdd(&g_sumprob[lane], spacc);
}

// ---------------- K2b: prefix offsets + aux loss ------------------------------
__global__ void k2b_prefix(float* out, int write_aux) {
    int lane = threadIdx.x;
    int c = g_cnt[lane];
    int sc = c;
#pragma unroll
    for (int o = 1; o < 32; o <<= 1) {
        int v = __shfl_up_sync(0xffffffffu, sc, o);
        if (lane >= o) sc += v;
    }
    g_off[lane] = sc - c;
    if (write_aux) {
        float v = g_sumprob[lane] * (float)c;
#pragma unroll
        for (int o = 16; o; o >>= 1) v += __shfl_xor_sync(0xffffffffu, v, o);
        if (lane == 0)
            out[OUT_ELEMS] = (float)N_EXP * v / ((float)N_TOK * (float)N_TOK);
    }
}

// ---------------- K3: down-proj partials, FFMA2, 64x64x64 tiles ----------------
// grid (16 k-slices, 32 experts), 256 threads. Per block: 64 tok x 64 l x 64 k.
__global__ __launch_bounds__(256, 3)
void k3_down(const float* __restrict__ x, const float* __restrict__ w_down) {
    __shared__ float ws[D_LOW * 66];      // [64 l][64 k + pad]
    __shared__ float xs[64 * 66];         // [64 tok][64 k + pad]
    __shared__ int   tokS[64];

    const int e = blockIdx.y;
    const int ks = blockIdx.x;
    const int cnt = g_cnt[e];
    if (cnt == 0) return;
    const int off = g_off[e];
    const int tid = threadIdx.x;

    // weights for this k-slice (loaded once)
    const float2* wd2 = (const float2*)w_down;
#pragma unroll
    for (int i = 0; i < 8; i++) {
        int j = tid + i * 256;            // 2048 f2
        int l = j >> 5, c = j & 31;
        float2 v = wd2[(e * D_LOW + l) * (D_MODEL / 2) + ks * 32 + c];
        *(float2*)(ws + l * 66 + 2 * c) = v;
    }

    const int tq = tid & 15;
    const int lq = tid >> 4;
    const float2* x2g = (const float2*)x;

    for (int t0 = 0; t0 < cnt; t0 += 64) {
        __syncthreads();
        if (tid < 64) {
            int idx = t0 + tid;
            tokS[tid] = g_btok[e * N_TOK + (idx < cnt ? idx : cnt - 1)];
        }
        __syncthreads();
#pragma unroll
        for (int i = 0; i < 8; i++) {
            int j = tid + i * 256;
            int r = j >> 5, c = j & 31;
            float2 v = x2g[tokS[r] * (D_MODEL / 2) + ks * 32 + c];
            *(float2*)(xs + r * 66 + 2 * c) = v;
        }
        __syncthreads();

        ull acc[4][4];
#pragma unroll
        for (int j = 0; j < 4; j++)
#pragma unroll
            for (int i = 0; i < 4; i++) acc[j][i] = 0ull;

#pragma unroll 8
        for (int k2 = 0; k2 < 32; k2++) {
            ull xv[4], wv[4];
#pragma unroll
            for (int j = 0; j < 4; j++)
                xv[j] = *(const ull*)(xs + (tq + 16 * j) * 66 + 2 * k2);
#pragma unroll
            for (int i = 0; i < 4; i++)
                wv[i] = *(const ull*)(ws + (lq * 4 + i) * 66 + 2 * k2);
#pragma unroll
            for (int j = 0; j < 4; j++)
#pragma unroll
                for (int i = 0; i < 4; i++)
                    FFMA2(acc[j][i], xv[j], wv[i]);
        }

        float4* ap4 = (float4*)g_actp;
#pragma unroll
        for (int j = 0; j < 4; j++) {
            int s = t0 + tq + 16 * j;
            if (s < cnt) {
                float4 v = make_float4(hsum2(acc[j][0]), hsum2(acc[j][1]),
                                       hsum2(acc[j][2]), hsum2(acc[j][3]));
                ap4[(ks * N_PAIR + off + s) * (D_LOW / 4) + lq] = v;
            }
        }
    }
}

// ---------------- K3g: sum 16 k-slices + GELU ----------------------------------
__global__ void k3g_gelu() {
    int i = blockIdx.x * 256 + threadIdx.x;       // 128*256 = 32768 f4 = PS/4
    const float4* ap4 = (const float4*)g_actp;
    float4 s = ap4[i];
#pragma unroll
    for (int k = 1; k < KSPLIT; k++) {
        float4 v = ap4[k * (PS / 4) + i];
        s.x += v.x; s.y += v.y; s.z += v.z; s.w += v.w;
    }
    ((float4*)g_acts)[i] = make_float4(gelu_exact(s.x), gelu_exact(s.y),
                                       gelu_exact(s.z), gelu_exact(s.w));
}

// ---------------- K4: up-proj, FFMA2, 64tok x 64d x 64l tiles ------------------
// grid (16 d-tiles, 32 experts), 256 threads.
__global__ __launch_bounds__(256, 3)
void k4_up(const float* __restrict__ w_up) {
    __shared__ float wu_s[64 * 66];       // [64 d][64 l + pad]  (transposed)
    __shared__ float as_s[64 * 66];       // [64 tok][64 l + pad]
    __shared__ float wgt_s[64];

    const int e = blockIdx.y;
    const int dt = blockIdx.x;
    const int cnt = g_cnt[e];
    if (cnt == 0) return;
    const int off = g_off[e];
    const int tid = threadIdx.x;

    // transpose w_up[e][l][dt*64 + d] -> wu_s[d][l]
    const float2* wu2 = (const float2*)w_up;
#pragma unroll
    for (int i = 0; i < 8; i++) {
        int j = tid + i * 256;            // 2048 f2: l = j>>5, dpair c = j&31
        int l = j >> 5, c = j & 31;
        float2 v = wu2[(e * D_LOW + l) * (D_MODEL / 2) + dt * 32 + c];
        wu_s[(2 * c + 0) * 66 + l] = v.x;
        wu_s[(2 * c + 1) * 66 + l] = v.y;
    }

    const int tq = tid & 15;
    const int dq = tid >> 4;
    const float2* a2g = (const float2*)g_acts;
    float4* y4 = (float4*)g_y;

    for (int t0 = 0; t0 < cnt; t0 += 64) {
        __syncthreads();
        if (tid < 64) {
            int idx = t0 + tid;
            wgt_s[tid] = (idx < cnt) ? g_bwgt[e * N_TOK + idx] : 0.f;
        }
#pragma unroll
        for (int i = 0; i < 8; i++) {
            int j = tid + i * 256;
            int r = j >> 5, c = j & 31;
            int idx = t0 + r;
            float2 v = a2g[(off + (idx < cnt ? idx : cnt - 1)) * (D_LOW / 2) + c];
            *(float2*)(as_s + r * 66 + 2 * c) = v;
        }
        __syncthreads();

        ull acc[4][4];
#pragma unroll
        for (int j = 0; j < 4; j++)
#pragma unroll
            for (int i = 0; i < 4; i++) acc[j][i] = 0ull;

#pragma unroll 8
        for (int l2 = 0; l2 < 32; l2++) {
            ull av[4], wv[4];
#pragma unroll
            for (int j = 0; j < 4; j++)
                av[j] = *(const ull*)(as_s + (tq + 16 * j) * 66 + 2 * l2);
#pragma unroll
            for (int i = 0; i < 4; i++)
                wv[i] = *(const ull*)(wu_s + (dq * 4 + i) * 66 + 2 * l2);
#pragma unroll
            for (int j = 0; j < 4; j++)
#pragma unroll
                for (int i = 0; i < 4; i++)
                    FFMA2(acc[j][i], av[j], wv[i]);
        }

#pragma unroll
        for (int j = 0; j < 4; j++) {
            int s = t0 + tq + 16 * j;
            if (s < cnt) {
                float w = wgt_s[tq + 16 * j];
                float4 v = make_float4(w * hsum2(acc[j][0]), w * hsum2(acc[j][1]),
                                       w * hsum2(acc[j][2]), w * hsum2(acc[j][3]));
                y4[(off + s) * (D_MODEL / 4) + dt * 16 + dq] = v;
            }
        }
    }
}

// ---------------- K5: gather-combine the two pairs per token ------------------
__global__ void k5_combine(float* __restrict__ out) {
    const int n = blockIdx.x;
    const int i = threadIdx.x;
    int v0 = g_pslot[n * 2 + 0];
    int v1 = g_pslot[n * 2 + 1];
    int p0 = g_off[v0 >> 10] + (v0 & (N_TOK - 1));
    int p1 = g_off[v1 >> 10] + (v1 & (N_TOK - 1));
    const float4* y4 = (const float4*)g_y;
    float4 a = y4[p0 * (D_MODEL / 4) + i];
    float4 b = y4[p1 * (D_MODEL / 4) + i];
    ((float4*)out)[n * (D_MODEL / 4) + i] =
        make_float4(a.x + b.x, a.y + b.y, a.z + b.z, a.w + b.w);
}

// ---------------- launch ------------------------------------------------------
extern "C" void kernel_launch(void* const* d_in, const int* in_sizes, int n_in,
                              void* d_out, int out_size) {
    const float* x        = (const float*)d_in[0];
    const float* w_down   = (const float*)d_in[1];
    const float* router_w = (const float*)d_in[2];
    const float* w_up     = (const float*)d_in[3];
    float* out = (float*)d_out;

    k1_fold<<<128, 256>>>(w_down, router_w);
    k2_route<<<32, 256>>>(x);
    k2b_prefix<<<1, 32>>>(out, out_size > OUT_ELEMS ? 1 : 0);
    k3_down<<<dim3(KSPLIT, N_EXP), 256>>>(x, w_down);
    k3g_gelu<<<128, 256>>>();
    k4_up<<<dim3(16, N_EXP), 256>>>(w_up);
    k5_combine<<<N_TOK, 256>>>(out);
}

// round 5
// speedup vs baseline: 1.7382x; 1.3699x over previous
#include <cuda_runtime.h>
#include <math.h>

#define D_MODEL 1024
#define N_EXP   32
#define D_LOW   64
#define N_TOK   1024
#define N_PAIR  (N_TOK * 2)
#define OUT_ELEMS (N_TOK * D_MODEL)
#define KSPLIT  16
#define PS      (N_PAIR * D_LOW)     // 131072 partials per k-slice

// ---------------- scratch ------------------------------------------------------
__device__ float g_wr[N_EXP * D_MODEL];
__device__ int   g_cnt[N_EXP];
__device__ float g_sumprob[N_EXP];
__device__ int   g_btok[N_EXP * N_TOK];
__device__ float g_bwgt[N_EXP * N_TOK];
__device__ int   g_pslot[N_TOK * 2];
__device__ float g_lgp[4 * N_TOK * N_EXP];   // k-split logit partials
__device__ float g_actp[KSPLIT * PS];        // k-split down-proj partials (8MB)
__device__ float g_acts[PS];                 // gelu(feats), pair-compact
__device__ float g_y[N_PAIR * D_MODEL];      // weighted per-pair up-proj output

// ---------------- helpers ------------------------------------------------------
typedef unsigned long long ull;
#define FFMA2(acc, a, b) asm("fma.rn.f32x2 %0, %1, %2, %0;" : "+l"(acc) : "l"(a), "l"(b))

__device__ __forceinline__ float hsum2(ull v) {
    return __uint_as_float((unsigned)v) + __uint_as_float((unsigned)(v >> 32));
}
__device__ __forceinline__ float dot4(float4 a, float4 b) {
    return a.x * b.x + a.y * b.y + a.z * b.z + a.w * b.w;
}
__device__ __forceinline__ float gelu_exact(float v) {
    return 0.5f * v * (1.0f + erff(v * 0.70710678118654752440f));
}
// exclusive prefix of g_cnt at expert e (warp-uniform helper, all 32 lanes)
__device__ __forceinline__ int expert_off(int lane, int e) {
    int cc = g_cnt[lane];
    int sc = cc;
#pragma unroll
    for (int o = 1; o < 32; o <<= 1) {
        int v = __shfl_up_sync(0xffffffffu, sc, o);
        if (lane >= o) sc += v;
    }
    return __shfl_sync(0xffffffffu, sc - cc, e);
}

// ---------------- K1: fold router_w into w_down -> g_wr; zero accumulators ----
__global__ void k1_fold(const float* __restrict__ w_down,
                        const float* __restrict__ router_w) {
    __shared__ float rs[D_LOW];
    int tid = threadIdx.x;
    if (blockIdx.x == 0 && tid < N_EXP) { g_cnt[tid] = 0; g_sumprob[tid] = 0.f; }
    if (tid < D_LOW) rs[tid] = router_w[tid];
    __syncthreads();
    int idx = blockIdx.x * 256 + tid;
    int e = idx >> 10;
    int d = idx & (D_MODEL - 1);
    const float* wb = w_down + (e << 6) * D_MODEL + d;
    float acc = 0.f;
#pragma unroll 8
    for (int l = 0; l < D_LOW; l++)
        acc = fmaf(wb[l * D_MODEL], rs[l], acc);
    g_wr[idx] = acc;
}

// ---------------- K2a: logits GEMM, k-split by 4 -------------------------------
// grid (32 token-tiles, 4 k-chunks), 256 threads. 32 tok x 32 exp x 256 k.
__global__ __launch_bounds__(256) void k2a_logits(const float* __restrict__ x) {
    __shared__ float4 xs4[32 * 33];
    __shared__ float4 wr4[32 * 33];
    const int tid = threadIdx.x;
    const int tt = blockIdx.x, kc = blockIdx.y;
    const int t = tid & 31, eg = tid >> 5;
    const float4* x4 = (const float4*)x;
    const float4* w4 = (const float4*)g_wr;

    float acc0 = 0.f, acc1 = 0.f, acc2 = 0.f, acc3 = 0.f;
    for (int sub = 0; sub < 2; sub++) {
        const int k0q = kc * 64 + sub * 32;
#pragma unroll
        for (int i = 0; i < 4; i++) {
            int j = tid + i * 256;
            int r = j >> 5, c = j & 31;
            xs4[r * 33 + c] = x4[(tt * 32 + r) * (D_MODEL / 4) + k0q + c];
            wr4[r * 33 + c] = w4[r * (D_MODEL / 4) + k0q + c];
        }
        __syncthreads();
#pragma unroll 8
        for (int k4 = 0; k4 < 32; k4++) {
            float4 xv = xs4[t * 33 + k4];
            acc0 += dot4(xv, wr4[(eg * 4 + 0) * 33 + k4]);
            acc1 += dot4(xv, wr4[(eg * 4 + 1) * 33 + k4]);
            acc2 += dot4(xv, wr4[(eg * 4 + 2) * 33 + k4]);
            acc3 += dot4(xv, wr4[(eg * 4 + 3) * 33 + k4]);
        }
        __syncthreads();
    }
    const int n = tt * 32 + t;
    ((float4*)g_lgp)[kc * (N_TOK * N_EXP / 4) + n * 8 + eg] =
        make_float4(acc0, acc1, acc2, acc3);
}

// ---------------- K2c: reduce partials + softmax + top-2 + bucketize ----------
// grid 128, 256 threads; one warp per token.
__global__ void k2c_route() {
    const int tid = threadIdx.x;
    const int lane = tid & 31, warp = tid >> 5;
    const int n = blockIdx.x * 8 + warp;

    float v = 0.f;
#pragma unroll
    for (int p = 0; p < 4; p++)
        v += g_lgp[p * (N_TOK * N_EXP) + n * N_EXP + lane];

    float m = v;
#pragma unroll
    for (int o = 16; o; o >>= 1) m = fmaxf(m, __shfl_xor_sync(0xffffffffu, m, o));
    float ex = expf(v - m);
    float s = ex;
#pragma unroll
    for (int o = 16; o; o >>= 1) s += __shfl_xor_sync(0xffffffffu, s, o);
    float prob = ex / s;
    atomicAdd(&g_sumprob[lane], prob);

    float bv = v; int bi = lane;
#pragma unroll
    for (int o = 16; o; o >>= 1) {
        float ov = __shfl_xor_sync(0xffffffffu, bv, o);
        int   oi = __shfl_xor_sync(0xffffffffu, bi, o);
        if (ov > bv || (ov == bv && oi < bi)) { bv = ov; bi = oi; }
    }
    int i0 = bi;
    float v2 = (lane == i0) ? -INFINITY : v;
    float bv2 = v2; int bi2 = lane;
#pragma unroll
    for (int o = 16; o; o >>= 1) {
        float ov = __shfl_xor_sync(0xffffffffu, bv2, o);
        int   oi = __shfl_xor_sync(0xffffffffu, bi2, o);
        if (ov > bv2 || (ov == bv2 && oi < bi2)) { bv2 = ov; bi2 = oi; }
    }
    int i1 = bi2;
    float p0 = __shfl_sync(0xffffffffu, prob, i0);
    float p1 = __shfl_sync(0xffffffffu, prob, i1);
    if (lane == 0) {
        float inv = 1.f / (p0 + p1);
        int s0 = atomicAdd(&g_cnt[i0], 1);
        g_btok[i0 * N_TOK + s0] = n;
        g_bwgt[i0 * N_TOK + s0] = p0 * inv;
        g_pslot[n * 2 + 0] = i0 * N_TOK + s0;
        int s1 = atomicAdd(&g_cnt[i1], 1);
        g_btok[i1 * N_TOK + s1] = n;
        g_bwgt[i1 * N_TOK + s1] = p1 * inv;
        g_pslot[n * 2 + 1] = i1 * N_TOK + s1;
    }
}

// ---------------- K3: down-proj partials, FFMA2, 32tok x 64l x 64k tiles -------
// grid (16 k-slices, 32 experts, 4 token-tiles), 256 threads.
__global__ __launch_bounds__(256)
void k3_down(const float* __restrict__ x, const float* __restrict__ w_down) {
    __shared__ float ws[D_LOW * 68];      // [64 l][64 k + pad]
    __shared__ float xs[32 * 68];         // [32 tok][64 k + pad]

    const int e = blockIdx.y;
    const int ks = blockIdx.x;
    const int cnt = g_cnt[e];
    const int tile0 = blockIdx.z * 32;
    if (tile0 >= cnt) return;
    const int tid = threadIdx.x;
    const int off = expert_off(tid & 31, e);

    const float4* wd4 = (const float4*)w_down;
#pragma unroll
    for (int i = 0; i < 4; i++) {
        int j = tid + i * 256;            // 1024 f4
        int l = j >> 4, cq = j & 15;
        *(float4*)(ws + l * 68 + cq * 4) =
            wd4[(e * D_LOW + l) * (D_MODEL / 4) + ks * 16 + cq];
    }

    const int tq = tid & 15;
    const int lq = tid >> 4;
    const float4* x4g = (const float4*)x;

    for (int t0 = tile0; t0 < cnt; t0 += 128) {
        __syncthreads();                  // ws ready / prev readers done
#pragma unroll
        for (int i = 0; i < 2; i++) {
            int j = tid + i * 256;        // 512 f4
            int r = j >> 4, cq = j & 15;
            int idx = t0 + r; if (idx >= cnt) idx = cnt - 1;
            int tok = g_btok[e * N_TOK + idx];
            *(float4*)(xs + r * 68 + cq * 4) =
                x4g[tok * (D_MODEL / 4) + ks * 16 + cq];
        }
        __syncthreads();

        ull aL[2][4], aH[2][4];
#pragma unroll
        for (int j = 0; j < 2; j++)
#pragma unroll
            for (int i = 0; i < 4; i++) { aL[j][i] = 0ull; aH[j][i] = 0ull; }

#pragma unroll
        for (int k4 = 0; k4 < 16; k4++) {
            ulonglong2 xv[2], wv[4];
            xv[0] = *(const ulonglong2*)(xs + tq * 68 + k4 * 4);
            xv[1] = *(const ulonglong2*)(xs + (tq + 16) * 68 + k4 * 4);
#pragma unroll
            for (int i = 0; i < 4; i++)
                wv[i] = *(const ulonglong2*)(ws + (lq * 4 + i) * 68 + k4 * 4);
#pragma unroll
            for (int j = 0; j < 2; j++)
#pragma unroll
                for (int i = 0; i < 4; i++) {
                    FFMA2(aL[j][i], xv[j].x, wv[i].x);
                    FFMA2(aH[j][i], xv[j].y, wv[i].y);
                }
        }

        float4* ap4 = (float4*)g_actp;
#pragma unroll
        for (int j = 0; j < 2; j++) {
            int s = t0 + tq + 16 * j;
            if (s < cnt) {
                float4 v = make_float4(hsum2(aL[j][0]) + hsum2(aH[j][0]),
                                       hsum2(aL[j][1]) + hsum2(aH[j][1]),
                                       hsum2(aL[j][2]) + hsum2(aH[j][2]),
                                       hsum2(aL[j][3]) + hsum2(aH[j][3]));
                ap4[(ks * N_PAIR + off + s) * (D_LOW / 4) + lq] = v;
            }
        }
    }
}

// ---------------- K3g: sum 16 k-slices + GELU (+ aux loss in block 0) ---------
__global__ void k3g_gelu(float* out, int write_aux) {
    int tid = threadIdx.x;
    if (blockIdx.x == 0 && tid < 32 && write_aux) {
        float v = g_sumprob[tid] * (float)g_cnt[tid];
#pragma unroll
        for (int o = 16; o; o >>= 1) v += __shfl_xor_sync(0xffffffffu, v, o);
        if (tid == 0)
            out[OUT_ELEMS] = (float)N_EXP * v / ((float)N_TOK * (float)N_TOK);
    }
    int i = blockIdx.x * 256 + tid;               // 128*256 = PS/4
    const float4* ap4 = (const float4*)g_actp;
    float4 s = ap4[i];
#pragma unroll
    for (int k = 1; k < KSPLIT; k++) {
        float4 v = ap4[k * (PS / 4) + i];
        s.x += v.x; s.y += v.y; s.z += v.z; s.w += v.w;
    }
    ((float4*)g_acts)[i] = make_float4(gelu_exact(s.x), gelu_exact(s.y),
                                       gelu_exact(s.z), gelu_exact(s.w));
}

// ---------------- K4: up-proj, FFMA2, 32tok x 64d x 64l tiles ------------------
// grid (16 d-tiles, 32 experts, 2 token-tiles), 256 threads.
__global__ __launch_bounds__(256)
void k4_up(const float* __restrict__ w_up) {
    __shared__ float wu_s[64 * 68];       // [64 d][64 l + pad]  (transposed)
    __shared__ float as_s[32 * 68];       // [32 tok][64 l + pad]

    const int e = blockIdx.y;
    const int dt = blockIdx.x;
    const int cnt = g_cnt[e];
    const int tile0 = blockIdx.z * 32;
    if (tile0 >= cnt) return;
    const int tid = threadIdx.x;
    const int off = expert_off(tid & 31, e);

    // transposed fill: coalesced column reads, conflict-free f4 smem stores
#pragma unroll
    for (int i = 0; i < 4; i++) {
        int j = tid + i * 256;            // 1024: d = j&63, l-group = j>>6
        int d = j & 63, lg = j >> 6;
        const float* base = w_up + (e * D_LOW + lg * 4) * D_MODEL + dt * 64 + d;
        *(float4*)(wu_s + d * 68 + lg * 4) =
            make_float4(base[0], base[D_MODEL], base[2 * D_MODEL], base[3 * D_MODEL]);
    }

    const int tq = tid & 15;
    const int dq = tid >> 4;
    const float4* a4g = (const float4*)g_acts;
    float4* y4 = (float4*)g_y;

    for (int t0 = tile0; t0 < cnt; t0 += 64) {
        __syncthreads();
#pragma unroll
        for (int i = 0; i < 2; i++) {
            int j = tid + i * 256;        // 512 f4
            int r = j >> 4, cq = j & 15;
            int idx = t0 + r; if (idx >= cnt) idx = cnt - 1;
            *(float4*)(as_s + r * 68 + cq * 4) =
                a4g[(off + idx) * (D_LOW / 4) + cq];
        }
        __syncthreads();

        ull aL[2][4], aH[2][4];
#pragma unroll
        for (int j = 0; j < 2; j++)
#pragma unroll
            for (int i = 0; i < 4; i++) { aL[j][i] = 0ull; aH[j][i] = 0ull; }

#pragma unroll
        for (int l4 = 0; l4 < 16; l4++) {
            ulonglong2 xv[2], wv[4];
            xv[0] = *(const ulonglong2*)(as_s + tq * 68 + l4 * 4);
            xv[1] = *(const ulonglong2*)(as_s + (tq + 16) * 68 + l4 * 4);
#pragma unroll
            for (int i = 0; i < 4; i++)
                wv[i] = *(const ulonglong2*)(wu_s + (dq * 4 + i) * 68 + l4 * 4);
#pragma unroll
            for (int j = 0; j < 2; j++)
#pragma unroll
                for (int i = 0; i < 4; i++) {
                    FFMA2(aL[j][i], xv[j].x, wv[i].x);
                    FFMA2(aH[j][i], xv[j].y, wv[i].y);
                }
        }

#pragma unroll
        for (int j = 0; j < 2; j++) {
            int s = t0 + tq + 16 * j;
            if (s < cnt) {
                float w = g_bwgt[e * N_TOK + s];
                float4 v = make_float4(w * (hsum2(aL[j][0]) + hsum2(aH[j][0])),
                                       w * (hsum2(aL[j][1]) + hsum2(aH[j][1])),
                                       w * (hsum2(aL[j][2]) + hsum2(aH[j][2])),
                                       w * (hsum2(aL[j][3]) + hsum2(aH[j][3])));
                y4[(off + s) * (D_MODEL / 4) + dt * 16 + dq] = v;
            }
        }
    }
}

// ---------------- K5: gather-combine the two pairs per token ------------------
__global__ void k5_combine(float* __restrict__ out) {
    const int n = blockIdx.x;
    const int tid = threadIdx.x;
    const int lane = tid & 31;
    // inline scan for offsets
    int cc = g_cnt[lane];
    int sc = cc;
#pragma unroll
    for (int o = 1; o < 32; o <<= 1) {
        int v = __shfl_up_sync(0xffffffffu, sc, o);
        if (lane >= o) sc += v;
    }
    int offl = sc - cc;
    int v0 = g_pslot[n * 2 + 0];
    int v1 = g_pslot[n * 2 + 1];
    int p0 = __shfl_sync(0xffffffffu, offl, v0 >> 10) + (v0 & (N_TOK - 1));
    int p1 = __shfl_sync(0xffffffffu, offl, v1 >> 10) + (v1 & (N_TOK - 1));
    const float4* y4 = (const float4*)g_y;
    float4 a = y4[p0 * (D_MODEL / 4) + tid];
    float4 b = y4[p1 * (D_MODEL / 4) + tid];
    ((float4*)out)[n * (D_MODEL / 4) + tid] =
        make_float4(a.x + b.x, a.y + b.y, a.z + b.z, a.w + b.w);
}

// ---------------- launch ------------------------------------------------------
extern "C" void kernel_launch(void* const* d_in, const int* in_sizes, int n_in,
                              void* d_out, int out_size) {
    const float* x        = (const float*)d_in[0];
    const float* w_down   = (const float*)d_in[1];
    const float* router_w = (const float*)d_in[2];
    const float* w_up     = (const float*)d_in[3];
    float* out = (float*)d_out;

    k1_fold<<<128, 256>>>(w_down, router_w);
    k2a_logits<<<dim3(32, 4), 256>>>(x);
    k2c_route<<<128, 256>>>();
    k3_down<<<dim3(KSPLIT, N_EXP, 4), 256>>>(x, w_down);
    k3g_gelu<<<128, 256>>>(out, out_size > OUT_ELEMS ? 1 : 0);
    k4_up<<<dim3(16, N_EXP, 2), 256>>>(w_up);
    k5_combine<<<N_TOK, 256>>>(out);
}

// round 7
// speedup vs baseline: 1.7402x; 1.0012x over previous
#include <cuda_runtime.h>
#include <math.h>

#define D_MODEL 1024
#define N_EXP   32
#define D_LOW   64
#define N_TOK   1024
#define N_PAIR  (N_TOK * 2)
#define OUT_ELEMS (N_TOK * D_MODEL)
#define KSPLIT  16
#define LSPLIT  8                    // k2a logit k-split
#define PS      (N_PAIR * D_LOW)     // 131072 partials per k-slice

// ---------------- scratch ------------------------------------------------------
__device__ float g_wr[N_EXP * D_MODEL];
__device__ int   g_cnt[N_EXP];
__device__ float g_sumprob[N_EXP];
__device__ int   g_btok[N_EXP * N_TOK];
__device__ float g_bwgt[N_EXP * N_TOK];
__device__ int   g_pslot[N_TOK * 2];
__device__ float g_lgp[LSPLIT * N_TOK * N_EXP];  // k-split logit partials
__device__ float g_actp[KSPLIT * PS];            // k-split down partials (8MB)
__device__ float g_acts[PS];                     // gelu(feats), pair-compact
__device__ float g_y[N_PAIR * D_MODEL];          // weighted per-pair up output

// ---------------- helpers ------------------------------------------------------
typedef unsigned long long ull;
#define FFMA2(acc, a, b) asm("fma.rn.f32x2 %0, %1, %2, %0;" : "+l"(acc) : "l"(a), "l"(b))

__device__ __forceinline__ float hsum2(ull v) {
    return __uint_as_float((unsigned)v) + __uint_as_float((unsigned)(v >> 32));
}
__device__ __forceinline__ float dot4(float4 a, float4 b) {
    return a.x * b.x + a.y * b.y + a.z * b.z + a.w * b.w;
}
__device__ __forceinline__ float gelu_exact(float v) {
    return 0.5f * v * (1.0f + erff(v * 0.70710678118654752440f));
}
// exclusive prefix of g_cnt at expert e (all 32 lanes participate)
__device__ __forceinline__ int expert_off(int lane, int e) {
    int cc = g_cnt[lane];
    int sc = cc;
#pragma unroll
    for (int o = 1; o < 32; o <<= 1) {
        int v = __shfl_up_sync(0xffffffffu, sc, o);
        if (lane >= o) sc += v;
    }
    return __shfl_sync(0xffffffffu, sc - cc, e);
}

// ---------------- K1: fold router_w into w_down -> g_wr; zero accumulators ----
__global__ void k1_fold(const float* __restrict__ w_down,
                        const float* __restrict__ router_w) {
    __shared__ float rs[D_LOW];
    int tid = threadIdx.x;
    if (blockIdx.x == 0 && tid < N_EXP) { g_cnt[tid] = 0; g_sumprob[tid] = 0.f; }
    if (tid < D_LOW) rs[tid] = router_w[tid];
    __syncthreads();
    int idx = blockIdx.x * 256 + tid;
    int e = idx >> 10;
    int d = idx & (D_MODEL - 1);
    const float* wb = w_down + (e << 6) * D_MODEL + d;
    float acc = 0.f;
#pragma unroll 8
    for (int l = 0; l < D_LOW; l++)
        acc = fmaf(wb[l * D_MODEL], rs[l], acc);
    g_wr[idx] = acc;
}

// ---------------- K2a: logits GEMM, k-split by 8 -------------------------------
// grid (32 token-tiles, 8 k-chunks), 256 threads. 32 tok x 32 exp x 128 k.
__global__ __launch_bounds__(256) void k2a_logits(const float* __restrict__ x) {
    __shared__ float4 xs4[32 * 33];
    __shared__ float4 wr4[32 * 33];
    const int tid = threadIdx.x;
    const int tt = blockIdx.x, kc = blockIdx.y;
    const int t = tid & 31, eg = tid >> 5;
    const float4* x4 = (const float4*)x;
    const float4* w4 = (const float4*)g_wr;

    const int k0q = kc * 32;
#pragma unroll
    for (int i = 0; i < 4; i++) {
        int j = tid + i * 256;
        int r = j >> 5, c = j & 31;
        xs4[r * 33 + c] = x4[(tt * 32 + r) * (D_MODEL / 4) + k0q + c];
        wr4[r * 33 + c] = w4[r * (D_MODEL / 4) + k0q + c];
    }
    __syncthreads();
    float acc0 = 0.f, acc1 = 0.f, acc2 = 0.f, acc3 = 0.f;
#pragma unroll 8
    for (int k4 = 0; k4 < 32; k4++) {
        float4 xv = xs4[t * 33 + k4];
        acc0 += dot4(xv, wr4[(eg * 4 + 0) * 33 + k4]);
        acc1 += dot4(xv, wr4[(eg * 4 + 1) * 33 + k4]);
        acc2 += dot4(xv, wr4[(eg * 4 + 2) * 33 + k4]);
        acc3 += dot4(xv, wr4[(eg * 4 + 3) * 33 + k4]);
    }
    const int n = tt * 32 + t;
    ((float4*)g_lgp)[kc * (N_TOK * N_EXP / 4) + n * 8 + eg] =
        make_float4(acc0, acc1, acc2, acc3);
}

// ---------------- K2c: reduce partials + softmax + top-2 + bucketize ----------
__global__ void k2c_route() {
    const int tid = threadIdx.x;
    const int lane = tid & 31, warp = tid >> 5;
    const int n = blockIdx.x * 8 + warp;

    float v = 0.f;
#pragma unroll
    for (int p = 0; p < LSPLIT; p++)
        v += g_lgp[p * (N_TOK * N_EXP) + n * N_EXP + lane];

    float m = v;
#pragma unroll
    for (int o = 16; o; o >>= 1) m = fmaxf(m, __shfl_xor_sync(0xffffffffu, m, o));
    float ex = expf(v - m);
    float s = ex;
#pragma unroll
    for (int o = 16; o; o >>= 1) s += __shfl_xor_sync(0xffffffffu, s, o);
    float prob = ex / s;
    atomicAdd(&g_sumprob[lane], prob);

    float bv = v; int bi = lane;
#pragma unroll
    for (int o = 16; o; o >>= 1) {
        float ov = __shfl_xor_sync(0xffffffffu, bv, o);
        int   oi = __shfl_xor_sync(0xffffffffu, bi, o);
        if (ov > bv || (ov == bv && oi < bi)) { bv = ov; bi = oi; }
    }
    int i0 = bi;
    float v2 = (lane == i0) ? -INFINITY : v;
    float bv2 = v2; int bi2 = lane;
#pragma unroll
    for (int o = 16; o; o >>= 1) {
        float ov = __shfl_xor_sync(0xffffffffu, bv2, o);
        int   oi = __shfl_xor_sync(0xffffffffu, bi2, o);
        if (ov > bv2 || (ov == bv2 && oi < bi2)) { bv2 = ov; bi2 = oi; }
    }
    int i1 = bi2;
    float p0 = __shfl_sync(0xffffffffu, prob, i0);
    float p1 = __shfl_sync(0xffffffffu, prob, i1);
    if (lane == 0) {
        float inv = 1.f / (p0 + p1);
        int s0 = atomicAdd(&g_cnt[i0], 1);
        g_btok[i0 * N_TOK + s0] = n;
        g_bwgt[i0 * N_TOK + s0] = p0 * inv;
        g_pslot[n * 2 + 0] = i0 * N_TOK + s0;
        int s1 = atomicAdd(&g_cnt[i1], 1);
        g_btok[i1 * N_TOK + s1] = n;
        g_bwgt[i1 * N_TOK + s1] = p1 * inv;
        g_pslot[n * 2 + 1] = i1 * N_TOK + s1;
    }
}

// ---------------- K3: down-proj partials, FFMA2, merged accs, reg-prefetch ----
// grid (16 k-slices, 32 experts, 4 token-tiles), 256 threads, 32-token tiles.
__global__ __launch_bounds__(256, 4)
void k3_down(const float* __restrict__ x, const float* __restrict__ w_down) {
    __shared__ float ws[D_LOW * 68];      // [64 l][64 k + pad]
    __shared__ float xs[32 * 68];         // [32 tok][64 k + pad]

    const int e = blockIdx.y;
    const int ks = blockIdx.x;
    const int cnt = g_cnt[e];
    const int tile0 = blockIdx.z * 32;
    if (tile0 >= cnt) return;
    const int tid = threadIdx.x;
    const int off = expert_off(tid & 31, e);

    const float4* wd4 = (const float4*)w_down;
#pragma unroll
    for (int i = 0; i < 4; i++) {
        int j = tid + i * 256;
        int l = j >> 4, cq = j & 15;
        *(float4*)(ws + l * 68 + cq * 4) =
            wd4[(e * D_LOW + l) * (D_MODEL / 4) + ks * 16 + cq];
    }

    const int tq = tid & 15;
    const int lq = tid >> 4;
    const int r0 = tid >> 4, cq0 = tid & 15;   // staging coords (r0, r0+16)
    const float4* x4g = (const float4*)x;

    // prefetch first tile into registers
    float4 xr0, xr1;
    {
        int i0 = tile0 + r0;      if (i0 >= cnt) i0 = cnt - 1;
        int i1 = tile0 + r0 + 16; if (i1 >= cnt) i1 = cnt - 1;
        xr0 = x4g[g_btok[e * N_TOK + i0] * (D_MODEL / 4) + ks * 16 + cq0];
        xr1 = x4g[g_btok[e * N_TOK + i1] * (D_MODEL / 4) + ks * 16 + cq0];
    }
    __syncthreads();   // ws ready

    for (int t0 = tile0; t0 < cnt; t0 += 128) {
        *(float4*)(xs + r0 * 68 + cq0 * 4) = xr0;
        *(float4*)(xs + (r0 + 16) * 68 + cq0 * 4) = xr1;
        __syncthreads();

        int tn = t0 + 128;
        if (tn < cnt) {           // prefetch next tile (overlaps compute)
            int i0 = tn + r0;      if (i0 >= cnt) i0 = cnt - 1;
            int i1 = tn + r0 + 16; if (i1 >= cnt) i1 = cnt - 1;
            xr0 = x4g[g_btok[e * N_TOK + i0] * (D_MODEL / 4) + ks * 16 + cq0];
            xr1 = x4g[g_btok[e * N_TOK + i1] * (D_MODEL / 4) + ks * 16 + cq0];
        }

        ull acc[2][4];
#pragma unroll
        for (int j = 0; j < 2; j++)
#pragma unroll
            for (int i = 0; i < 4; i++) acc[j][i] = 0ull;

#pragma unroll
        for (int k4 = 0; k4 < 16; k4++) {
            ulonglong2 xv0 = *(const ulonglong2*)(xs + tq * 68 + k4 * 4);
            ulonglong2 xv1 = *(const ulonglong2*)(xs + (tq + 16) * 68 + k4 * 4);
            ulonglong2 wv[4];
#pragma unroll
            for (int i = 0; i < 4; i++)
                wv[i] = *(const ulonglong2*)(ws + (lq * 4 + i) * 68 + k4 * 4);
#pragma unroll
            for (int i = 0; i < 4; i++) {
                FFMA2(acc[0][i], xv0.x, wv[i].x);
                FFMA2(acc[0][i], xv0.y, wv[i].y);
                FFMA2(acc[1][i], xv1.x, wv[i].x);
                FFMA2(acc[1][i], xv1.y, wv[i].y);
            }
        }

        float4* ap4 = (float4*)g_actp;
#pragma unroll
        for (int j = 0; j < 2; j++) {
            int s = t0 + tq + 16 * j;
            if (s < cnt) {
                float4 v = make_float4(hsum2(acc[j][0]), hsum2(acc[j][1]),
                                       hsum2(acc[j][2]), hsum2(acc[j][3]));
                ap4[(ks * N_PAIR + off + s) * (D_LOW / 4) + lq] = v;
            }
        }
        __syncthreads();
    }
}

// ---------------- K3g: sum 16 k-slices + GELU (+ aux loss in block 0) ---------
__global__ void k3g_gelu(float* out, int write_aux) {
    int tid = threadIdx.x;
    if (blockIdx.x == 0 && tid < 32 && write_aux) {
        float v = g_sumprob[tid] * (float)g_cnt[tid];
#pragma unroll
        for (int o = 16; o; o >>= 1) v += __shfl_xor_sync(0xffffffffu, v, o);
        if (tid == 0)
            out[OUT_ELEMS] = (float)N_EXP * v / ((float)N_TOK * (float)N_TOK);
    }
    int i = blockIdx.x * 256 + tid;               // 128*256 = PS/4
    const float4* ap4 = (const float4*)g_actp;
    float4 s = ap4[i];
#pragma unroll
    for (int k = 1; k < KSPLIT; k++) {
        float4 v = ap4[k * (PS / 4) + i];
        s.x += v.x; s.y += v.y; s.z += v.z; s.w += v.w;
    }
    ((float4*)g_acts)[i] = make_float4(gelu_exact(s.x), gelu_exact(s.y),
                                       gelu_exact(s.z), gelu_exact(s.w));
}

// ---------------- K4: up-proj, FFMA2, merged accs, reg-prefetch ----------------
// grid (16 d-tiles, 32 experts, 2 token-tiles), 256 threads.
__global__ __launch_bounds__(256, 4)
void k4_up(const float* __restrict__ w_up) {
    __shared__ float wu_s[64 * 68];       // [64 d][64 l + pad]  (transposed)
    __shared__ float as_s[32 * 68];       // [32 tok][64 l + pad]

    const int e = blockIdx.y;
    const int dt = blockIdx.x;
    const int cnt = g_cnt[e];
    const int tile0 = blockIdx.z * 32;
    if (tile0 >= cnt) return;
    const int tid = threadIdx.x;
    const int off = expert_off(tid & 31, e);

    // transposed fill: coalesced column reads, conflict-free f4 smem stores
#pragma unroll
    for (int i = 0; i < 4; i++) {
        int j = tid + i * 256;
        int d = j & 63, lg = j >> 6;
        const float* base = w_up + (e * D_LOW + lg * 4) * D_MODEL + dt * 64 + d;
        *(float4*)(wu_s + d * 68 + lg * 4) =
            make_float4(base[0], base[D_MODEL], base[2 * D_MODEL], base[3 * D_MODEL]);
    }

    const int tq = tid & 15;
    const int dq = tid >> 4;
    const int r0 = tid >> 4, cq0 = tid & 15;
    const float4* a4g = (const float4*)g_acts;
    float4* y4 = (float4*)g_y;

    float4 ar0, ar1;
    {
        int i0 = tile0 + r0;      if (i0 >= cnt) i0 = cnt - 1;
        int i1 = tile0 + r0 + 16; if (i1 >= cnt) i1 = cnt - 1;
        ar0 = a4g[(off + i0) * (D_LOW / 4) + cq0];
        ar1 = a4g[(off + i1) * (D_LOW / 4) + cq0];
    }
    __syncthreads();   // wu_s ready

    for (int t0 = tile0; t0 < cnt; t0 += 64) {
        *(float4*)(as_s + r0 * 68 + cq0 * 4) = ar0;
        *(float4*)(as_s + (r0 + 16) * 68 + cq0 * 4) = ar1;
        __syncthreads();

        int tn = t0 + 64;
        if (tn < cnt) {
            int i0 = tn + r0;      if (i0 >= cnt) i0 = cnt - 1;
            int i1 = tn + r0 + 16; if (i1 >= cnt) i1 = cnt - 1;
            ar0 = a4g[(off + i0) * (D_LOW / 4) + cq0];
            ar1 = a4g[(off + i1) * (D_LOW / 4) + cq0];
        }

        ull acc[2][4];
#pragma unroll
        for (int j = 0; j < 2; j++)
#pragma unroll
            for (int i = 0; i < 4; i++) acc[j][i] = 0ull;

#pragma unroll
        for (int l4 = 0; l4 < 16; l4++) {
            ulonglong2 xv0 = *(const ulonglong2*)(as_s + tq * 68 + l4 * 4);
            ulonglong2 xv1 = *(const ulonglong2*)(as_s + (tq + 16) * 68 + l4 * 4);
            ulonglong2 wv[4];
#pragma unroll
            for (int i = 0; i < 4; i++)
                wv[i] = *(const ulonglong2*)(wu_s + (dq * 4 + i) * 68 + l4 * 4);
#pragma unroll
            for (int i = 0; i < 4; i++) {
                FFMA2(acc[0][i], xv0.x, wv[i].x);
                FFMA2(acc[0][i], xv0.y, wv[i].y);
                FFMA2(acc[1][i], xv1.x, wv[i].x);
                FFMA2(acc[1][i], xv1.y, wv[i].y);
            }
        }

#pragma unroll
        for (int j = 0; j < 2; j++) {
            int s = t0 + tq + 16 * j;
            if (s < cnt) {
                float w = g_bwgt[e * N_TOK + s];
                float4 v = make_float4(w * hsum2(acc[j][0]), w * hsum2(acc[j][1]),
                                       w * hsum2(acc[j][2]), w * hsum2(acc[j][3]));
                y4[(off + s) * (D_MODEL / 4) + dt * 16 + dq] = v;
            }
        }
        __syncthreads();
    }
}

// ---------------- K5: gather-combine the two pairs per token ------------------
__global__ void k5_combine(float* __restrict__ out) {
    const int n = blockIdx.x;
    const int tid = threadIdx.x;
    const int lane = tid & 31;
    int cc = g_cnt[lane];
    int sc = cc;
#pragma unroll
    for (int o = 1; o < 32; o <<= 1) {
        int v = __shfl_up_sync(0xffffffffu, sc, o);
        if (lane >= o) sc += v;
    }
    int offl = sc - cc;
    int v0 = g_pslot[n * 2 + 0];
    int v1 = g_pslot[n * 2 + 1];
    int p0 = __shfl_sync(0xffffffffu, offl, v0 >> 10) + (v0 & (N_TOK - 1));
    int p1 = __shfl_sync(0xffffffffu, offl, v1 >> 10) + (v1 & (N_TOK - 1));
    const float4* y4 = (const float4*)g_y;
    float4 a = y4[p0 * (D_MODEL / 4) + tid];
    float4 b = y4[p1 * (D_MODEL / 4) + tid];
    ((float4*)out)[n * (D_MODEL / 4) + tid] =
        make_float4(a.x + b.x, a.y + b.y, a.z + b.z, a.w + b.w);
}

// ---------------- launch ------------------------------------------------------
extern "C" void kernel_launch(void* const* d_in, const int* in_sizes, int n_in,
                              void* d_out, int out_size) {
    const float* x        = (const float*)d_in[0];
    const float* w_down   = (const float*)d_in[1];
    const float* router_w = (const float*)d_in[2];
    const float* w_up     = (const float*)d_in[3];
    float* out = (float*)d_out;

    k1_fold<<<128, 256>>>(w_down, router_w);
    k2a_logits<<<dim3(32, LSPLIT), 256>>>(x);
    k2c_route<<<128, 256>>>();
    k3_down<<<dim3(KSPLIT, N_EXP, 4), 256>>>(x, w_down);
    k3g_gelu<<<128, 256>>>(out, out_size > OUT_ELEMS ? 1 : 0);
    k4_up<<<dim3(16, N_EXP, 2), 256>>>(w_up);
    k5_combine<<<N_TOK, 256>>>(out);
}

// round 8
// speedup vs baseline: 1.8806x; 1.0807x over previous
#include <cuda_runtime.h>
#include <math.h>

#define D_MODEL 1024
#define N_EXP   32
#define D_LOW   64
#define N_TOK   1024
#define N_PAIR  (N_TOK * 2)
#define OUT_ELEMS (N_TOK * D_MODEL)
#define KSPLIT  16
#define LSPLIT  8                    // k2a logit k-split
#define PS      (N_PAIR * D_LOW)     // 131072 partials per k-slice

// ---------------- scratch ------------------------------------------------------
__device__ float g_wr[N_EXP * D_MODEL];
__device__ int   g_cnt[N_EXP];
__device__ float g_sumprob[N_EXP];
__device__ int   g_btok[N_EXP * N_TOK];
__device__ float g_bwgt[N_EXP * N_TOK];
__device__ int   g_pslot[N_TOK * 2];
__device__ float g_lgp[LSPLIT * N_TOK * N_EXP];  // k-split logit partials
__device__ float g_actp[KSPLIT * PS];            // k-split down partials (8MB)
__device__ float g_acts[PS];                     // gelu(feats), pair-compact
__device__ float g_y[N_PAIR * D_MODEL];          // weighted per-pair up output

// ---------------- helpers ------------------------------------------------------
typedef unsigned long long ull;
#define FFMA2(acc, a, b) asm("fma.rn.f32x2 %0, %1, %2, %0;" : "+l"(acc) : "l"(a), "l"(b))

__device__ __forceinline__ float hsum2(ull v) {
    return __uint_as_float((unsigned)v) + __uint_as_float((unsigned)(v >> 32));
}
__device__ __forceinline__ float dot4(float4 a, float4 b) {
    return a.x * b.x + a.y * b.y + a.z * b.z + a.w * b.w;
}
__device__ __forceinline__ float gelu_exact(float v) {
    return 0.5f * v * (1.0f + erff(v * 0.70710678118654752440f));
}
// exclusive prefix of g_cnt at expert e (all 32 lanes participate)
__device__ __forceinline__ int expert_off(int lane, int e) {
    int cc = g_cnt[lane];
    int sc = cc;
#pragma unroll
    for (int o = 1; o < 32; o <<= 1) {
        int v = __shfl_up_sync(0xffffffffu, sc, o);
        if (lane >= o) sc += v;
    }
    return __shfl_sync(0xffffffffu, sc - cc, e);
}

// ---------------- K1: fold router_w into w_down -> g_wr; zero accumulators ----
__global__ void k1_fold(const float* __restrict__ w_down,
                        const float* __restrict__ router_w) {
    __shared__ float rs[D_LOW];
    int tid = threadIdx.x;
    if (blockIdx.x == 0 && tid < N_EXP) { g_cnt[tid] = 0; g_sumprob[tid] = 0.f; }
    if (tid < D_LOW) rs[tid] = router_w[tid];
    __syncthreads();
    int idx = blockIdx.x * 256 + tid;
    int e = idx >> 10;
    int d = idx & (D_MODEL - 1);
    const float* wb = w_down + (e << 6) * D_MODEL + d;
    float acc = 0.f;
#pragma unroll 8
    for (int l = 0; l < D_LOW; l++)
        acc = fmaf(wb[l * D_MODEL], rs[l], acc);
    g_wr[idx] = acc;
}

// ---------------- K2a: logits GEMM, k-split by 8 -------------------------------
__global__ __launch_bounds__(256) void k2a_logits(const float* __restrict__ x) {
    __shared__ float4 xs4[32 * 33];
    __shared__ float4 wr4[32 * 33];
    const int tid = threadIdx.x;
    const int tt = blockIdx.x, kc = blockIdx.y;
    const int t = tid & 31, eg = tid >> 5;
    const float4* x4 = (const float4*)x;
    const float4* w4 = (const float4*)g_wr;

    const int k0q = kc * 32;
#pragma unroll
    for (int i = 0; i < 4; i++) {
        int j = tid + i * 256;
        int r = j >> 5, c = j & 31;
        xs4[r * 33 + c] = x4[(tt * 32 + r) * (D_MODEL / 4) + k0q + c];
        wr4[r * 33 + c] = w4[r * (D_MODEL / 4) + k0q + c];
    }
    __syncthreads();
    float acc0 = 0.f, acc1 = 0.f, acc2 = 0.f, acc3 = 0.f;
#pragma unroll 8
    for (int k4 = 0; k4 < 32; k4++) {
        float4 xv = xs4[t * 33 + k4];
        acc0 += dot4(xv, wr4[(eg * 4 + 0) * 33 + k4]);
        acc1 += dot4(xv, wr4[(eg * 4 + 1) * 33 + k4]);
        acc2 += dot4(xv, wr4[(eg * 4 + 2) * 33 + k4]);
        acc3 += dot4(xv, wr4[(eg * 4 + 3) * 33 + k4]);
    }
    const int n = tt * 32 + t;
    ((float4*)g_lgp)[kc * (N_TOK * N_EXP / 4) + n * 8 + eg] =
        make_float4(acc0, acc1, acc2, acc3);
}

// ---------------- K2c: reduce partials + softmax + top-2 + bucketize ----------
__global__ void k2c_route() {
    const int tid = threadIdx.x;
    const int lane = tid & 31, warp = tid >> 5;
    const int n = blockIdx.x * 8 + warp;

    float v = 0.f;
#pragma unroll
    for (int p = 0; p < LSPLIT; p++)
        v += g_lgp[p * (N_TOK * N_EXP) + n * N_EXP + lane];

    float m = v;
#pragma unroll
    for (int o = 16; o; o >>= 1) m = fmaxf(m, __shfl_xor_sync(0xffffffffu, m, o));
    float ex = expf(v - m);
    float s = ex;
#pragma unroll
    for (int o = 16; o; o >>= 1) s += __shfl_xor_sync(0xffffffffu, s, o);
    float prob = ex / s;
    atomicAdd(&g_sumprob[lane], prob);

    float bv = v; int bi = lane;
#pragma unroll
    for (int o = 16; o; o >>= 1) {
        float ov = __shfl_xor_sync(0xffffffffu, bv, o);
        int   oi = __shfl_xor_sync(0xffffffffu, bi, o);
        if (ov > bv || (ov == bv && oi < bi)) { bv = ov; bi = oi; }
    }
    int i0 = bi;
    float v2 = (lane == i0) ? -INFINITY : v;
    float bv2 = v2; int bi2 = lane;
#pragma unroll
    for (int o = 16; o; o >>= 1) {
        float ov = __shfl_xor_sync(0xffffffffu, bv2, o);
        int   oi = __shfl_xor_sync(0xffffffffu, bi2, o);
        if (ov > bv2 || (ov == bv2 && oi < bi2)) { bv2 = ov; bi2 = oi; }
    }
    int i1 = bi2;
    float p0 = __shfl_sync(0xffffffffu, prob, i0);
    float p1 = __shfl_sync(0xffffffffu, prob, i1);
    if (lane == 0) {
        float inv = 1.f / (p0 + p1);
        int s0 = atomicAdd(&g_cnt[i0], 1);
        g_btok[i0 * N_TOK + s0] = n;
        g_bwgt[i0 * N_TOK + s0] = p0 * inv;
        g_pslot[n * 2 + 0] = i0 * N_TOK + s0;
        int s1 = atomicAdd(&g_cnt[i1], 1);
        g_btok[i1 * N_TOK + s1] = n;
        g_bwgt[i1 * N_TOK + s1] = p1 * inv;
        g_pslot[n * 2 + 1] = i1 * N_TOK + s1;
    }
}

// ---------------- K3: down-proj partials, FFMA2, 64tok x 64l x 64k, acc[4][4] -
// grid (16 k-slices, 32 experts, 2 token-tiles), 256 threads.
__global__ __launch_bounds__(256, 3)
void k3_down(const float* __restrict__ x, const float* __restrict__ w_down) {
    __shared__ float ws[D_LOW * 68];      // [64 l][64 k + pad]
    __shared__ float xs[64 * 68];         // [64 tok][64 k + pad]

    const int e = blockIdx.y;
    const int ks = blockIdx.x;
    const int cnt = g_cnt[e];
    const int tile0 = blockIdx.z * 64;
    if (tile0 >= cnt) return;
    const int tid = threadIdx.x;
    const int off = expert_off(tid & 31, e);

    const float4* wd4 = (const float4*)w_down;
#pragma unroll
    for (int i = 0; i < 4; i++) {
        int j = tid + i * 256;
        int l = j >> 4, cq = j & 15;
        *(float4*)(ws + l * 68 + cq * 4) =
            wd4[(e * D_LOW + l) * (D_MODEL / 4) + ks * 16 + cq];
    }

    const int tq = tid & 15;            // token group (4 tokens: +0,16,32,48)
    const int lq = tid >> 4;            // 16 groups x 4 l = 64 l
    const int r0 = tid >> 4, cq0 = tid & 15;
    const float4* x4g = (const float4*)x;

    for (int t0 = tile0; t0 < cnt; t0 += 128) {
#pragma unroll
        for (int j = 0; j < 4; j++) {
            int idx = t0 + r0 + 16 * j; if (idx >= cnt) idx = cnt - 1;
            *(float4*)(xs + (r0 + 16 * j) * 68 + cq0 * 4) =
                x4g[g_btok[e * N_TOK + idx] * (D_MODEL / 4) + ks * 16 + cq0];
        }
        __syncthreads();

        ull acc[4][4];
#pragma unroll
        for (int j = 0; j < 4; j++)
#pragma unroll
            for (int i = 0; i < 4; i++) acc[j][i] = 0ull;

#pragma unroll
        for (int k4i = 0; k4i < 16; k4i++) {
            ulonglong2 xv[4], wv[4];
#pragma unroll
            for (int j = 0; j < 4; j++)
                xv[j] = *(const ulonglong2*)(xs + (tq + 16 * j) * 68 + k4i * 4);
#pragma unroll
            for (int i = 0; i < 4; i++)
                wv[i] = *(const ulonglong2*)(ws + (lq * 4 + i) * 68 + k4i * 4);
#pragma unroll
            for (int j = 0; j < 4; j++)
#pragma unroll
                for (int i = 0; i < 4; i++) {
                    FFMA2(acc[j][i], xv[j].x, wv[i].x);
                    FFMA2(acc[j][i], xv[j].y, wv[i].y);
                }
        }

        float4* ap4 = (float4*)g_actp;
#pragma unroll
        for (int j = 0; j < 4; j++) {
            int s = t0 + tq + 16 * j;
            if (s < cnt) {
                float4 v = make_float4(hsum2(acc[j][0]), hsum2(acc[j][1]),
                                       hsum2(acc[j][2]), hsum2(acc[j][3]));
                ap4[(ks * N_PAIR + off + s) * (D_LOW / 4) + lq] = v;
            }
        }
        __syncthreads();
    }
}

// ---------------- K3g: sum 16 k-slices + GELU (+ aux loss in block 0) ---------
__global__ void k3g_gelu(float* out, int write_aux) {
    int tid = threadIdx.x;
    if (blockIdx.x == 0 && tid < 32 && write_aux) {
        float v = g_sumprob[tid] * (float)g_cnt[tid];
#pragma unroll
        for (int o = 16; o; o >>= 1) v += __shfl_xor_sync(0xffffffffu, v, o);
        if (tid == 0)
            out[OUT_ELEMS] = (float)N_EXP * v / ((float)N_TOK * (float)N_TOK);
    }
    int i = blockIdx.x * 256 + tid;               // 128*256 = PS/4
    const float4* ap4 = (const float4*)g_actp;
    float4 s = ap4[i];
#pragma unroll
    for (int k = 1; k < KSPLIT; k++) {
        float4 v = ap4[k * (PS / 4) + i];
        s.x += v.x; s.y += v.y; s.z += v.z; s.w += v.w;
    }
    ((float4*)g_acts)[i] = make_float4(gelu_exact(s.x), gelu_exact(s.y),
                                       gelu_exact(s.z), gelu_exact(s.w));
}

// ---------------- K4: up-proj, FFMA2, 64tok x 64d x 64l, acc[4][4] -------------
// grid (16 d-tiles, 32 experts, 2 token-tiles), 256 threads.
__global__ __launch_bounds__(256, 3)
void k4_up(const float* __restrict__ w_up) {
    __shared__ float wu_s[64 * 68];       // [64 d][64 l + pad]  (transposed)
    __shared__ float as_s[64 * 68];       // [64 tok][64 l + pad]

    const int e = blockIdx.y;
    const int dt = blockIdx.x;
    const int cnt = g_cnt[e];
    const int tile0 = blockIdx.z * 64;
    if (tile0 >= cnt) return;
    const int tid = threadIdx.x;
    const int off = expert_off(tid & 31, e);

    // transpose w_up[e][l][dt*64 + d] -> wu_s[d][l]
#pragma unroll
    for (int i = 0; i < 4; i++) {
        int j = tid + i * 256;
        int d = j & 63, lg = j >> 6;
        const float* base = w_up + (e * D_LOW + lg * 4) * D_MODEL + dt * 64 + d;
        *(float4*)(wu_s + d * 68 + lg * 4) =
            make_float4(base[0], base[D_MODEL], base[2 * D_MODEL], base[3 * D_MODEL]);
    }

    const int tq = tid & 15;            // 4 tokens: +0,16,32,48
    const int dq = tid >> 4;            // 16 groups x 4 d = 64 d
    const int r0 = tid >> 4, cq0 = tid & 15;
    const float4* a4g = (const float4*)g_acts;
    float4* y4 = (float4*)g_y;

    for (int t0 = tile0; t0 < cnt; t0 += 128) {
#pragma unroll
        for (int j = 0; j < 4; j++) {
            int idx = t0 + r0 + 16 * j; if (idx >= cnt) idx = cnt - 1;
            *(float4*)(as_s + (r0 + 16 * j) * 68 + cq0 * 4) =
                a4g[(off + idx) * (D_LOW / 4) + cq0];
        }
        __syncthreads();

        ull acc[4][4];
#pragma unroll
        for (int j = 0; j < 4; j++)
#pragma unroll
            for (int i = 0; i < 4; i++) acc[j][i] = 0ull;

#pragma unroll
        for (int l4 = 0; l4 < 16; l4++) {
            ulonglong2 xv[4], wv[4];
#pragma unroll
            for (int j = 0; j < 4; j++)
                xv[j] = *(const ulonglong2*)(as_s + (tq + 16 * j) * 68 + l4 * 4);
#pragma unroll
            for (int i = 0; i < 4; i++)
                wv[i] = *(const ulonglong2*)(wu_s + (dq * 4 + i) * 68 + l4 * 4);
#pragma unroll
            for (int j = 0; j < 4; j++)
#pragma unroll
                for (int i = 0; i < 4; i++) {
                    FFMA2(acc[j][i], xv[j].x, wv[i].x);
                    FFMA2(acc[j][i], xv[j].y, wv[i].y);
                }
        }

#pragma unroll
        for (int j = 0; j < 4; j++) {
            int s = t0 + tq + 16 * j;
            if (s < cnt) {
                float w = g_bwgt[e * N_TOK + s];
                float4 v = make_float4(w * hsum2(acc[j][0]), w * hsum2(acc[j][1]),
                                       w * hsum2(acc[j][2]), w * hsum2(acc[j][3]));
                y4[(off + s) * (D_MODEL / 4) + dt * 16 + dq] = v;
            }
        }
        __syncthreads();
    }
}

// ---------------- K5: gather-combine the two pairs per token ------------------
__global__ void k5_combine(float* __restrict__ out) {
    const int n = blockIdx.x;
    const int tid = threadIdx.x;
    const int lane = tid & 31;
    int cc = g_cnt[lane];
    int sc = cc;
#pragma unroll
    for (int o = 1; o < 32; o <<= 1) {
        int v = __shfl_up_sync(0xffffffffu, sc, o);
        if (lane >= o) sc += v;
    }
    int offl = sc - cc;
    int v0 = g_pslot[n * 2 + 0];
    int v1 = g_pslot[n * 2 + 1];
    int p0 = __shfl_sync(0xffffffffu, offl, v0 >> 10) + (v0 & (N_TOK - 1));
    int p1 = __shfl_sync(0xffffffffu, offl, v1 >> 10) + (v1 & (N_TOK - 1));
    const float4* y4 = (const float4*)g_y;
    float4 a = y4[p0 * (D_MODEL / 4) + tid];
    float4 b = y4[p1 * (D_MODEL / 4) + tid];
    ((float4*)out)[n * (D_MODEL / 4) + tid] =
        make_float4(a.x + b.x, a.y + b.y, a.z + b.z, a.w + b.w);
}

// ---------------- launch ------------------------------------------------------
extern "C" void kernel_launch(void* const* d_in, const int* in_sizes, int n_in,
                              void* d_out, int out_size) {
    const float* x        = (const float*)d_in[0];
    const float* w_down   = (const float*)d_in[1];
    const float* router_w = (const float*)d_in[2];
    const float* w_up     = (const float*)d_in[3];
    float* out = (float*)d_out;

    k1_fold<<<128, 256>>>(w_down, router_w);
    k2a_logits<<<dim3(32, LSPLIT), 256>>>(x);
    k2c_route<<<128, 256>>>();
    k3_down<<<dim3(KSPLIT, N_EXP, 2), 256>>>(x, w_down);
    k3g_gelu<<<128, 256>>>(out, out_size > OUT_ELEMS ? 1 : 0);
    k4_up<<<dim3(16, N_EXP, 2), 256>>>(w_up);
    k5_combine<<<N_TOK, 256>>>(out);
}